// round 10
// baseline (speedup 1.0000x reference)
#include <cuda_runtime.h>
#include <cstdint>

// Dims: N=32, K=32, T=128, H=768
#define NN 32
#define KK 32
#define TT 128
#define HH 768
#define H2 1536

// Output layout (float32 concat)
#define OFF_SCORE 0
#define OFF_ENC   1024
#define OFF_MASK  (1024 + 3145728)
#define OFF_USE   (OFF_MASK + 4096)
#define OFF_IDX   (OFF_USE + 24576)

// Scratch
__device__ float g_cqk[NN * HH];   // cqk_pro [n][g] (bias folded)
__device__ float g_v[NN * HH];     // v [n][h]
__device__ float g_c[NN];          // b_k . cqk_pro[n]

// K1 block ranges
#define KA_BLOCKS  192             // kA: 4 g-rows/block, x staged in smem
#define PF_BLOCKS  16
#define ENC_BLOCKS 384             // enc copy: 3072 warp-jobs x 256 f4 (MLP 8)
#define USE_BLOCKS 6
#define MSK_BLOCKS 32
#define PF_BASE   KA_BLOCKS
#define ENC_BASE  (PF_BASE + PF_BLOCKS)
#define USE_BASE  (ENC_BASE + ENC_BLOCKS)
#define MSK_BASE  (USE_BASE + USE_BLOCKS)
#define K1_BLOCKS (MSK_BASE + MSK_BLOCKS)     // 630

// ---------------------------------------------------------------------------
// K1: fused [kA (smem-staged x, FMA-bound) | L2 prefetch | gather]
//   kA: block = 4 g x 32 n. 6 t-chunks of 256; x chunk staged in smem once
//   per block (L2 x-traffic 151MB -> 4MB). Warp pair per g splits n 16/16.
// ---------------------------------------------------------------------------
__global__ void __launch_bounds__(256) k1_fused(
    const float* __restrict__ ctx,      // (N,3,H)
    const float* __restrict__ tracked,  // (N,H)
    const float* __restrict__ W_cqk,    // (H,2H)
    const float* __restrict__ b_cqk,    // (H,)
    const float* __restrict__ p0,       // (N,K,T,H)
    const float* __restrict__ p1,       // (N,K,H)
    const int*   __restrict__ pmask,    // (N,K,T) bool-as-int32
    const int*   __restrict__ label,    // (N,)
    const int*   __restrict__ ptok,     // (N,K,T)
    const float* __restrict__ W_k,      // (H,H)
    float* __restrict__ out)
{
    __shared__ float4 x_s[NN * 65];             // [n][64 f4] stride 65, 33 KB

    int blk  = blockIdx.x;
    int tid  = threadIdx.x;
    int lane = tid & 31;

    if (blk < KA_BLOCKS) {
        // ---- kA ----
        int w     = tid >> 5;                   // 0..7
        int g     = blk * 4 + (w >> 1);
        int nhalf = w & 1;
        int nbase = nhalf * 16;

        const float4* W4 = reinterpret_cast<const float4*>(W_cqk + (size_t)g * H2);

        float acc[16];
#pragma unroll
        for (int nn = 0; nn < 16; ++nn) acc[nn] = 0.f;

        for (int chunk = 0; chunk < 6; ++chunk) {
            __syncthreads();
            // stage x[n][chunk*256 .. +255]: 2048 f4, 8 per thread, coalesced
#pragma unroll
            for (int kq = 0; kq < 8; ++kq) {
                int m    = tid + kq * 256;      // 0..2047
                int n    = m >> 6;              // 64 f4 per row
                int f4c  = m & 63;
                float4 v;
                if (chunk < 3)
                    v = reinterpret_cast<const float4*>(
                        ctx + ((size_t)n * 3 + 2) * HH)[chunk * 64 + f4c];
                else
                    v = reinterpret_cast<const float4*>(
                        tracked + (size_t)n * HH)[(chunk - 3) * 64 + f4c];
                x_s[n * 65 + f4c] = v;
            }
            __syncthreads();

#pragma unroll
            for (int u = 0; u < 2; ++u) {
                int j = u * 32 + lane;          // f4 index within chunk
                float4 wv = W4[chunk * 64 + j];
#pragma unroll
                for (int nn = 0; nn < 16; ++nn) {
                    float4 xv = x_s[(nbase + nn) * 65 + j];
                    float s = acc[nn];
                    s = fmaf(wv.x, xv.x, s); s = fmaf(wv.y, xv.y, s);
                    s = fmaf(wv.z, xv.z, s); s = fmaf(wv.w, xv.w, s);
                    acc[nn] = s;
                }
            }
        }

        float bg = __ldg(b_cqk + g);
#pragma unroll
        for (int nn = 0; nn < 16; ++nn) {
            float s = acc[nn];
#pragma unroll
            for (int o = 16; o > 0; o >>= 1) s += __shfl_down_sync(0xffffffffu, s, o);
            if (lane == 0) g_cqk[(size_t)(nbase + nn) * HH + g] = s + bg;
        }
        return;
    }

    if (blk < ENC_BASE) {
        // ---- L2 prefetch: W_k (2.25MB) + p1 (3MB) ----
        int pidx = (blk - PF_BASE) * 256 + tid;
        const char* b2 = (const char*)W_k;
        for (int i = pidx; i < 18432; i += PF_BLOCKS * 256)
            asm volatile("prefetch.global.L2 [%0];" :: "l"(b2 + (size_t)i * 128));
        const char* b1 = (const char*)p1;
        for (int i = pidx; i < 24576; i += PF_BLOCKS * 256)
            asm volatile("prefetch.global.L2 [%0];" :: "l"(b1 + (size_t)i * 128));
        return;
    }

    if (blk < USE_BASE) {
        // ---- enc copy: warp-job = 256 contiguous f4 within one n (MLP 8) ----
        int wjob = (blk - ENC_BASE) * 8 + (tid >> 5);   // 0..3071
        int n  = wjob / 96;                             // 96 jobs per n
        int r0 = (wjob - n * 96) * 256;
        int lab = __ldg(label + n);
        const float4* src = reinterpret_cast<const float4*>(
            p0 + ((size_t)(n * KK + lab)) * TT * HH);
        float4* dst = reinterpret_cast<float4*>(out + OFF_ENC + (size_t)n * TT * HH);

        float4 v[8];
#pragma unroll
        for (int u = 0; u < 8; ++u) v[u] = src[r0 + u * 32 + lane];
#pragma unroll
        for (int u = 0; u < 8; ++u) dst[r0 + u * 32 + lane] = v[u];
        return;
    }

    if (blk < MSK_BASE) {
        // ---- use copy: 6144 f4, thread handles 4 ----
        int t = (blk - USE_BASE) * 256 + tid;           // 0..1535
        float4 v[4];
        int idx[4];
#pragma unroll
        for (int u = 0; u < 4; ++u) {
            int i = t + u * 1536;                       // 0..6143
            int n = i / 192;
            int r = i - n * 192;
            int lab = __ldg(label + n);
            idx[u] = n * 192 + r;
            v[u] = reinterpret_cast<const float4*>(
                p1 + ((size_t)(n * KK + lab)) * HH)[r];
        }
#pragma unroll
        for (int u = 0; u < 4; ++u)
            reinterpret_cast<float4*>(out + OFF_USE)[idx[u]] = v[u];
        return;
    }

    // ---- mask + idx: 8192 scalar items ----
    {
        int i = (blk - MSK_BASE) * 256 + tid;           // 0..8191
        const int MT = NN * TT;                         // 4096
        if (i < MT) {
            int n = i / TT;
            int t = i - n * TT;
            int lab = __ldg(label + n);
            out[OFF_MASK + i] = (pmask[((size_t)(n * KK + lab)) * TT + t] != 0) ? 1.0f : 0.0f;
        } else {
            int j = i - MT;
            int n = j / TT;
            int t = j - n * TT;
            int lab = __ldg(label + n);
            out[OFF_IDX + j] = (float)ptok[((size_t)(n * KK + lab)) * TT + t];
        }
    }
}

// ---------------------------------------------------------------------------
// K2: v[n,h] = sum_g cqk[n,g] * W_k[g,h]  — float4 W loads
//   96 compute blocks x 256 thr; block 96 computes c[n].
// ---------------------------------------------------------------------------
__global__ void __launch_bounds__(256) k2_v(
    const float* __restrict__ W_k,   // (H,H)
    const float* __restrict__ b_k)   // (H,)
{
    __shared__ float sc[HH * 9];                 // [g][nn] stride 9, 27.6 KB
    __shared__ float4 red[32 * 64];              // [gsub][hf4*8+nn], 32 KB

    int blk = blockIdx.x;
    int tid = threadIdx.x;

    if (blk < 96) {
        int ngrp = blk / 24;
        int ht   = blk - ngrp * 24;
        int n0   = ngrp * 8;
        int h0   = ht * 32;
        int gsub = tid >> 3;                     // 0..31
        int hf4  = tid & 7;                      // 0..7
        int h    = h0 + hf4 * 4;

        for (int s = tid; s < 8 * HH; s += 256) {
            int nn = s / HH;
            int g  = s - nn * HH;
            sc[g * 9 + nn] = g_cqk[(size_t)(n0 + nn) * HH + g];
        }
        __syncthreads();

        float4 acc[8];
#pragma unroll
        for (int nn = 0; nn < 8; ++nn) acc[nn] = make_float4(0.f, 0.f, 0.f, 0.f);

        int g0 = gsub * 24;
#pragma unroll 6
        for (int i = 0; i < 24; ++i) {
            int g = g0 + i;
            float4 wv = __ldg(reinterpret_cast<const float4*>(
                W_k + (size_t)g * HH + h));
#pragma unroll
            for (int nn = 0; nn < 8; ++nn) {
                float x = sc[g * 9 + nn];
                acc[nn].x = fmaf(wv.x, x, acc[nn].x);
                acc[nn].y = fmaf(wv.y, x, acc[nn].y);
                acc[nn].z = fmaf(wv.z, x, acc[nn].z);
                acc[nn].w = fmaf(wv.w, x, acc[nn].w);
            }
        }

#pragma unroll
        for (int nn = 0; nn < 8; ++nn) red[gsub * 64 + hf4 * 8 + nn] = acc[nn];
        __syncthreads();

        if (tid < 64) {
            int ohf4 = tid >> 3;
            int onn  = tid & 7;
            float4 s = make_float4(0.f, 0.f, 0.f, 0.f);
#pragma unroll
            for (int gs = 0; gs < 32; ++gs) {
                float4 p = red[gs * 64 + tid];
                s.x += p.x; s.y += p.y; s.z += p.z; s.w += p.w;
            }
            *reinterpret_cast<float4*>(
                g_v + (size_t)(n0 + onn) * HH + h0 + ohf4 * 4) = s;
        }
        return;
    }

    // ---- c[n] = b_k . cqk[n,:]  (block 96) ----
    __shared__ float cred[32 * 9];
    int n = tid >> 3;
    int q = tid & 7;
    float s = 0.f;
    for (int i = 0; i < 96; ++i) {
        int g = q * 96 + i;
        s = fmaf(__ldg(b_k + g), g_cqk[(size_t)n * HH + g], s);
    }
    cred[n * 9 + q] = s;
    __syncthreads();
    if (tid < 32) {
        float t = 0.f;
#pragma unroll
        for (int j = 0; j < 8; ++j) t += cred[tid * 9 + j];
        g_c[tid] = t;
    }
}

// ---------------------------------------------------------------------------
// K3: score[n,k] = p1[n,k,:].v[n,:] + c[n], masked. Warp per (n,k).
// ---------------------------------------------------------------------------
__global__ void __launch_bounds__(256) k3_score(
    const float* __restrict__ p1,        // (N,K,H)
    const int* __restrict__ ck_mask,     // (N,K) bool-as-int32
    float* __restrict__ out)
{
    int wid  = blockIdx.x * 8 + (threadIdx.x >> 5);
    int lane = threadIdx.x & 31;
    int n = wid / KK;
    int k = wid - n * KK;

    const float4* p4 = reinterpret_cast<const float4*>(p1 + ((size_t)n * KK + k) * HH);
    const float4* v4 = reinterpret_cast<const float4*>(g_v + (size_t)n * HH);

    float4 a[6], b[6];
#pragma unroll
    for (int i = 0; i < 6; ++i) {
        int j = lane + 32 * i;
        a[i] = p4[j];
        b[i] = v4[j];
    }
    float s = 0.f;
#pragma unroll
    for (int i = 0; i < 6; ++i) {
        s = fmaf(a[i].x, b[i].x, s); s = fmaf(a[i].y, b[i].y, s);
        s = fmaf(a[i].z, b[i].z, s); s = fmaf(a[i].w, b[i].w, s);
    }
#pragma unroll
    for (int o = 16; o > 0; o >>= 1) s += __shfl_down_sync(0xffffffffu, s, o);
    if (lane == 0) {
        s += g_c[n];
        if (ck_mask[n * KK + k] == 0) s = -1e20f;
        out[OFF_SCORE + n * KK + k] = s;
    }
}

extern "C" void kernel_launch(void* const* d_in, const int* in_sizes, int n_in,
                              void* d_out, int out_size) {
    const float* ctx     = (const float*)d_in[0];
    const float* tracked = (const float*)d_in[1];
    const float* p0      = (const float*)d_in[2];
    const float* p1      = (const float*)d_in[3];
    const int*   pmask   = (const int*)d_in[4];
    const int*   ckmask  = (const int*)d_in[5];
    const int*   label   = (const int*)d_in[6];
    const int*   ptok    = (const int*)d_in[7];
    const float* W_cqk   = (const float*)d_in[8];
    const float* b_cqk   = (const float*)d_in[9];
    const float* W_k     = (const float*)d_in[10];
    const float* b_k     = (const float*)d_in[11];
    float* out = (float*)d_out;

    k1_fused<<<K1_BLOCKS, 256>>>(ctx, tracked, W_cqk, b_cqk,
                                 p0, p1, pmask, label, ptok, W_k, out);
    k2_v<<<97, 256>>>(W_k, b_k);
    k3_score<<<(NN * KK) / 8, 256>>>(p1, ckmask, out);
}

// round 11
// speedup vs baseline: 1.0214x; 1.0214x over previous
#include <cuda_runtime.h>
#include <cstdint>

// Dims: N=32, K=32, T=128, H=768
#define NN 32
#define KK 32
#define TT 128
#define HH 768
#define H2 1536

// Output layout (float32 concat)
#define OFF_SCORE 0
#define OFF_ENC   1024
#define OFF_MASK  (1024 + 3145728)
#define OFF_USE   (OFF_MASK + 4096)
#define OFF_IDX   (OFF_USE + 24576)

#define GRID_BLOCKS 296
#define THREADS     256

// Phase-0 roles
#define KA_BLOCKS   192                       // blocks [0,192): kA
#define CP_BLOCKS   104                       // blocks [192,296): copy/prefetch
#define CP_STRIDE   (CP_BLOCKS * THREADS)     // 26624

// Scratch
__device__ float g_cqk[NN * HH];   // cqk_pro [n][g] (bias folded)
__device__ float g_v[NN * HH];     // v [n][h]
__device__ float g_c[NN];          // b_k . cqk_pro[n]

// Monotonic grid barriers (never reset; graph replays serialize, so each
// replay forms its own generation via the ticket count).
__device__ unsigned g_bar0, g_bar1;

__device__ __forceinline__ void grid_barrier(unsigned* bar) {
    __syncthreads();
    if (threadIdx.x == 0) {
        __threadfence();
        unsigned t = atomicAdd(bar, 1u);
        unsigned target = (t / GRID_BLOCKS + 1u) * GRID_BLOCKS;
        volatile unsigned* p = bar;
        while (*p < target) __nanosleep(32);
        __threadfence();
    }
    __syncthreads();
}

// Shared scratch union:
//  phase0 kA : float4 x_s[32*65]            = 33280 B
//  phase1 v  : float sc[768*9] (27648 B) + float4 red[16*64] (16384 B) = 44032 B
#define SM_BYTES 44032

__global__ void __launch_bounds__(THREADS, 2) k_all(
    const float* __restrict__ ctx,      // (N,3,H)
    const float* __restrict__ tracked,  // (N,H)
    const float* __restrict__ W_cqk,    // (H,2H)
    const float* __restrict__ b_cqk,    // (H,)
    const float* __restrict__ p0,       // (N,K,T,H)
    const float* __restrict__ p1,       // (N,K,H)
    const int*   __restrict__ pmask,    // (N,K,T) bool-as-int32
    const int*   __restrict__ label,    // (N,)
    const int*   __restrict__ ptok,     // (N,K,T)
    const int*   __restrict__ ck_mask,  // (N,K) bool-as-int32
    const float* __restrict__ W_k,      // (H,H)
    const float* __restrict__ b_k,      // (H,)
    float* __restrict__ out)
{
    __shared__ __align__(16) unsigned char sm[SM_BYTES];

    int blk  = blockIdx.x;
    int tid  = threadIdx.x;
    int lane = tid & 31;

    // ======================= PHASE 0 =======================
    if (blk < KA_BLOCKS) {
        // ---- kA: block = 4 g x 32 n, x staged in smem (validated R10) ----
        float4* x_s = reinterpret_cast<float4*>(sm);    // [n][64 f4] stride 65

        int w     = tid >> 5;                   // 0..7
        int g     = blk * 4 + (w >> 1);
        int nbase = (w & 1) * 16;

        const float4* W4 = reinterpret_cast<const float4*>(W_cqk + (size_t)g * H2);

        float acc[16];
#pragma unroll
        for (int nn = 0; nn < 16; ++nn) acc[nn] = 0.f;

        for (int chunk = 0; chunk < 6; ++chunk) {
            __syncthreads();
#pragma unroll
            for (int kq = 0; kq < 8; ++kq) {
                int m   = tid + kq * 256;       // 0..2047
                int n   = m >> 6;
                int f4c = m & 63;
                float4 v;
                if (chunk < 3)
                    v = reinterpret_cast<const float4*>(
                        ctx + ((size_t)n * 3 + 2) * HH)[chunk * 64 + f4c];
                else
                    v = reinterpret_cast<const float4*>(
                        tracked + (size_t)n * HH)[(chunk - 3) * 64 + f4c];
                x_s[n * 65 + f4c] = v;
            }
            __syncthreads();

#pragma unroll
            for (int u = 0; u < 2; ++u) {
                int j = u * 32 + lane;
                float4 wv = W4[chunk * 64 + j];
#pragma unroll
                for (int nn = 0; nn < 16; ++nn) {
                    float4 xv = x_s[(nbase + nn) * 65 + j];
                    float s = acc[nn];
                    s = fmaf(wv.x, xv.x, s); s = fmaf(wv.y, xv.y, s);
                    s = fmaf(wv.z, xv.z, s); s = fmaf(wv.w, xv.w, s);
                    acc[nn] = s;
                }
            }
        }

        float bg = __ldg(b_cqk + g);
#pragma unroll
        for (int nn = 0; nn < 16; ++nn) {
            float s = acc[nn];
#pragma unroll
            for (int o = 16; o > 0; o >>= 1) s += __shfl_down_sync(0xffffffffu, s, o);
            if (lane == 0) g_cqk[(size_t)(nbase + nn) * HH + g] = s + bg;
        }
    } else {
        // ---- copy/prefetch role ----
        int cid  = blk - KA_BLOCKS;             // 0..103
        int base = cid * THREADS + tid;         // 0..26623

        // L2 prefetch: W_k (18432 lines) + p1 (24576 lines); <=1 line each
        {
            const char* b2 = (const char*)W_k;
            if (base < 18432)
                asm volatile("prefetch.global.L2 [%0];" :: "l"(b2 + (size_t)base * 128));
            const char* b1 = (const char*)p1;
            if (base < 24576)
                asm volatile("prefetch.global.L2 [%0];" :: "l"(b1 + (size_t)base * 128));
        }

        // use copy: 6144 f4 (cid 0..23, one each)
        if (base < 6144) {
            int n = base / 192;
            int r = base - n * 192;
            int lab = __ldg(label + n);
            reinterpret_cast<float4*>(out + OFF_USE)[n * 192 + r] =
                reinterpret_cast<const float4*>(p1 + ((size_t)(n * KK + lab)) * HH)[r];
        }
        // mask + idx: 8192 items
        if (base < 8192) {
            const int MT = NN * TT;             // 4096
            if (base < MT) {
                int n = base / TT;
                int t = base - n * TT;
                int lab = __ldg(label + n);
                out[OFF_MASK + base] = (pmask[((size_t)(n * KK + lab)) * TT + t] != 0) ? 1.0f : 0.0f;
            } else {
                int j = base - MT;
                int n = j / TT;
                int t = j - n * TT;
                int lab = __ldg(label + n);
                out[OFF_IDX + j] = (float)ptok[((size_t)(n * KK + lab)) * TT + t];
            }
        }

        // enc copy: 786432 f4, MLP-4 batched grid-stride
        const int ENC_F4 = NN * TT * HH / 4;    // 786432
        const int PER_N  = TT * HH / 4;         // 24576
        for (int j0 = base; j0 < ENC_F4; j0 += CP_STRIDE * 4) {
            float4 v[4];
            int di[4];
#pragma unroll
            for (int u = 0; u < 4; ++u) {
                int j = j0 + u * CP_STRIDE;
                di[u] = -1;
                if (j < ENC_F4) {
                    int n = j / PER_N;
                    int r = j - n * PER_N;
                    int lab = __ldg(label + n);
                    v[u] = reinterpret_cast<const float4*>(
                        p0 + ((size_t)(n * KK + lab)) * TT * HH)[r];
                    di[u] = n * PER_N + r;
                }
            }
#pragma unroll
            for (int u = 0; u < 4; ++u)
                if (di[u] >= 0)
                    reinterpret_cast<float4*>(out + OFF_ENC)[di[u]] = v[u];
        }
    }

    grid_barrier(&g_bar0);

    // ======================= PHASE 1 =======================
    if (blk < 96) {
        // v[n,h] = sum_g cqk[n,g] * W_k[g,h]   (validated R9 math, cascaded red)
        float*  sc  = reinterpret_cast<float*>(sm);            // [g][nn] stride 9
        float4* red = reinterpret_cast<float4*>(sm + 27648);   // 16*64 float4

        int ngrp = blk / 24;
        int ht   = blk - ngrp * 24;
        int n0   = ngrp * 8;
        int h0   = ht * 32;
        int gsub = tid >> 3;                    // 0..31
        int hf4  = tid & 7;                     // 0..7
        int h    = h0 + hf4 * 4;

        for (int s = tid; s < 8 * HH; s += THREADS) {
            int nn = s / HH;
            int g  = s - nn * HH;
            sc[g * 9 + nn] = g_cqk[(size_t)(n0 + nn) * HH + g];
        }
        __syncthreads();

        float4 acc[8];
#pragma unroll
        for (int nn = 0; nn < 8; ++nn) acc[nn] = make_float4(0.f, 0.f, 0.f, 0.f);

        int g0 = gsub * 24;
#pragma unroll 6
        for (int i = 0; i < 24; ++i) {
            int g = g0 + i;
            float4 wv = __ldg(reinterpret_cast<const float4*>(W_k + (size_t)g * HH + h));
#pragma unroll
            for (int nn = 0; nn < 8; ++nn) {
                float x = sc[g * 9 + nn];
                acc[nn].x = fmaf(wv.x, x, acc[nn].x);
                acc[nn].y = fmaf(wv.y, x, acc[nn].y);
                acc[nn].z = fmaf(wv.z, x, acc[nn].z);
                acc[nn].w = fmaf(wv.w, x, acc[nn].w);
            }
        }

        // cascaded halving over gsub (32 -> 1), 16KB buffer
#pragma unroll
        for (int step = 16; step >= 1; step >>= 1) {
            if (gsub >= step && gsub < 2 * step) {
#pragma unroll
                for (int nn = 0; nn < 8; ++nn)
                    red[(gsub - step) * 64 + hf4 * 8 + nn] = acc[nn];
            }
            __syncthreads();
            if (gsub < step) {
#pragma unroll
                for (int nn = 0; nn < 8; ++nn) {
                    float4 p = red[gsub * 64 + hf4 * 8 + nn];
                    acc[nn].x += p.x; acc[nn].y += p.y;
                    acc[nn].z += p.z; acc[nn].w += p.w;
                }
            }
            __syncthreads();
        }

        if (gsub == 0) {
#pragma unroll
            for (int nn = 0; nn < 8; ++nn)
                *reinterpret_cast<float4*>(
                    g_v + (size_t)(n0 + nn) * HH + h0 + hf4 * 4) = acc[nn];
        }
    } else if (blk == 96) {
        // c[n] = b_k . cqk[n,:]
        float* cred = reinterpret_cast<float*>(sm);     // 32*9
        int n = tid >> 3;
        int q = tid & 7;
        float s = 0.f;
        for (int i = 0; i < 96; ++i) {
            int g = q * 96 + i;
            s = fmaf(__ldg(b_k + g), g_cqk[(size_t)n * HH + g], s);
        }
        cred[n * 9 + q] = s;
        __syncthreads();
        if (tid < 32) {
            float t = 0.f;
#pragma unroll
            for (int j = 0; j < 8; ++j) t += cred[tid * 9 + j];
            g_c[tid] = t;
        }
    }

    grid_barrier(&g_bar1);

    // ======================= PHASE 2 =======================
    if (blk < 128) {
        int wjob = blk * 8 + (tid >> 5);        // 0..1023
        int n = wjob / KK;
        int k = wjob - n * KK;

        const float4* p4 = reinterpret_cast<const float4*>(p1 + ((size_t)n * KK + k) * HH);
        const float4* v4 = reinterpret_cast<const float4*>(g_v + (size_t)n * HH);

        float4 a[6], b[6];
#pragma unroll
        for (int i = 0; i < 6; ++i) {
            int j = lane + 32 * i;
            a[i] = p4[j];
            b[i] = v4[j];
        }
        float s = 0.f;
#pragma unroll
        for (int i = 0; i < 6; ++i) {
            s = fmaf(a[i].x, b[i].x, s); s = fmaf(a[i].y, b[i].y, s);
            s = fmaf(a[i].z, b[i].z, s); s = fmaf(a[i].w, b[i].w, s);
        }
#pragma unroll
        for (int o = 16; o > 0; o >>= 1) s += __shfl_down_sync(0xffffffffu, s, o);
        if (lane == 0) {
            s += g_c[n];
            if (ck_mask[n * KK + k] == 0) s = -1e20f;
            out[OFF_SCORE + n * KK + k] = s;
        }
    }
}

extern "C" void kernel_launch(void* const* d_in, const int* in_sizes, int n_in,
                              void* d_out, int out_size) {
    const float* ctx     = (const float*)d_in[0];
    const float* tracked = (const float*)d_in[1];
    const float* p0      = (const float*)d_in[2];
    const float* p1      = (const float*)d_in[3];
    const int*   pmask   = (const int*)d_in[4];
    const int*   ckmask  = (const int*)d_in[5];
    const int*   label   = (const int*)d_in[6];
    const int*   ptok    = (const int*)d_in[7];
    const float* W_cqk   = (const float*)d_in[8];
    const float* b_cqk   = (const float*)d_in[9];
    const float* W_k     = (const float*)d_in[10];
    const float* b_k     = (const float*)d_in[11];
    float* out = (float*)d_out;

    k_all<<<GRID_BLOCKS, THREADS>>>(ctx, tracked, W_cqk, b_cqk,
                                    p0, p1, pmask, label, ptok, ckmask,
                                    W_k, b_k, out);
}

// round 12
// speedup vs baseline: 1.0748x; 1.0523x over previous
#include <cuda_runtime.h>
#include <cstdint>

// Dims: N=32, K=32, T=128, H=768
#define NN 32
#define KK 32
#define TT 128
#define HH 768
#define H2 1536

// Output layout (float32 concat)
#define OFF_SCORE 0
#define OFF_ENC   1024
#define OFF_MASK  (1024 + 3145728)
#define OFF_USE   (OFF_MASK + 4096)
#define OFF_IDX   (OFF_USE + 24576)

// Scratch
__device__ float g_cqk[NN * HH];        // cqk_pro [n][g] (bias folded)
__device__ float g_c[NN];               // b_k . cqk_pro[n]
__device__ float g_spart[24 * 1024];    // partial scores [ht][n*32+k]
__device__ unsigned g_tick;             // monotonic ticket (mod 97)

// K1 block ranges (R7 structure, verbatim — best validated bench)
#define KA_BLOCKS 384              // kA: 3072 warps = (g 768) x (ngrp 4)
#define PF_BLOCKS 16
#define KD_ITEMS  (786432 + 6144 + 4096 + 4096)   // 800768
#define KD_BLOCKS ((KD_ITEMS + 255) / 256)        // 3128
#define K1_BLOCKS (KA_BLOCKS + PF_BLOCKS + KD_BLOCKS)

// ---------------------------------------------------------------------------
// K1: fused [kA (8-way n-blocked GEMV) | L2 prefetch | gather]  (R7 verbatim)
// ---------------------------------------------------------------------------
__global__ void __launch_bounds__(256) k1_fused(
    const float* __restrict__ ctx,      // (N,3,H)
    const float* __restrict__ tracked,  // (N,H)
    const float* __restrict__ W_cqk,    // (H,2H)
    const float* __restrict__ b_cqk,    // (H,)
    const float* __restrict__ p0,       // (N,K,T,H)
    const float* __restrict__ p1,       // (N,K,H)
    const int*   __restrict__ pmask,    // (N,K,T) bool-as-int32
    const int*   __restrict__ label,    // (N,)
    const int*   __restrict__ ptok,     // (N,K,T)
    const float* __restrict__ W_k,      // (H,H)
    float* __restrict__ out)
{
    int blk = blockIdx.x;
    int tid = threadIdx.x;

    if (blk < KA_BLOCKS) {
        // ---- kA: warp = (g, ngroup of 8 n); lanes split W row ----
        int gw   = blk * 8 + (tid >> 5);        // 0..3071
        int lane = tid & 31;
        int g    = gw >> 2;
        int n0   = (gw & 3) * 8;

        const float4* W4 = reinterpret_cast<const float4*>(W_cqk + (size_t)g * H2);

        float acc[8];
#pragma unroll
        for (int nn = 0; nn < 8; ++nn) acc[nn] = 0.f;

#pragma unroll
        for (int i = 0; i < 6; ++i) {
            int j = lane + 32 * i;              // 0..191
            float4 w  = W4[j];
            float4 w2 = W4[192 + j];
#pragma unroll
            for (int nn = 0; nn < 8; ++nn) {
                int n = n0 + nn;
                float4 x  = reinterpret_cast<const float4*>(
                    ctx + ((size_t)n * 3 + 2) * HH)[j];
                float4 x2 = reinterpret_cast<const float4*>(
                    tracked + (size_t)n * HH)[j];
                float s = acc[nn];
                s = fmaf(w.x,  x.x,  s); s = fmaf(w.y,  x.y,  s);
                s = fmaf(w.z,  x.z,  s); s = fmaf(w.w,  x.w,  s);
                s = fmaf(w2.x, x2.x, s); s = fmaf(w2.y, x2.y, s);
                s = fmaf(w2.z, x2.z, s); s = fmaf(w2.w, x2.w, s);
                acc[nn] = s;
            }
        }
        float bg = __ldg(b_cqk + g);
#pragma unroll
        for (int nn = 0; nn < 8; ++nn) {
            float s = acc[nn];
#pragma unroll
            for (int o = 16; o > 0; o >>= 1) s += __shfl_down_sync(0xffffffffu, s, o);
            if (lane == 0) g_cqk[(size_t)(n0 + nn) * HH + g] = s + bg;
        }
        return;
    }

    if (blk < KA_BLOCKS + PF_BLOCKS) {
        // ---- L2 prefetch: p1 (3MB) + W_k (2.25MB) ----
        int pidx = (blk - KA_BLOCKS) * 256 + tid;
        const char* b1 = (const char*)p1;
        const char* b2 = (const char*)W_k;
        for (int i = pidx; i < 24576; i += PF_BLOCKS * 256)
            asm volatile("prefetch.global.L2 [%0];" :: "l"(b1 + (size_t)i * 128));
        for (int i = pidx; i < 18432; i += PF_BLOCKS * 256)
            asm volatile("prefetch.global.L2 [%0];" :: "l"(b2 + (size_t)i * 128));
        return;
    }

    // ---- gather ----
    int idx = (blk - KA_BLOCKS - PF_BLOCKS) * 256 + tid;
    const int ENC_F4 = NN * TT * HH / 4;        // 786432
    const int USE_F4 = NN * HH / 4;             // 6144
    const int MT     = NN * TT;                 // 4096

    if (idx < ENC_F4) {
        int per_n = TT * HH / 4;                // 24576
        int n = idx / per_n;
        int r = idx - n * per_n;
        int lab = __ldg(label + n);
        const float4* src = reinterpret_cast<const float4*>(
            p0 + ((size_t)(n * KK + lab)) * TT * HH);
        float4* dst = reinterpret_cast<float4*>(out + OFF_ENC + (size_t)n * TT * HH);
        dst[r] = src[r];
        return;
    }
    idx -= ENC_F4;
    if (idx < USE_F4) {
        int per_n = HH / 4;                     // 192
        int n = idx / per_n;
        int r = idx - n * per_n;
        int lab = __ldg(label + n);
        const float4* src = reinterpret_cast<const float4*>(
            p1 + ((size_t)(n * KK + lab)) * HH);
        float4* dst = reinterpret_cast<float4*>(out + OFF_USE + (size_t)n * HH);
        dst[r] = src[r];
        return;
    }
    idx -= USE_F4;
    if (idx < MT) {
        int n = idx / TT;
        int t = idx - n * TT;
        int lab = __ldg(label + n);
        out[OFF_MASK + idx] = (pmask[((size_t)(n * KK + lab)) * TT + t] != 0) ? 1.0f : 0.0f;
        return;
    }
    idx -= MT;
    if (idx < MT) {
        int n = idx / TT;
        int t = idx - n * TT;
        int lab = __ldg(label + n);
        out[OFF_IDX + idx] = (float)ptok[((size_t)(n * KK + lab)) * TT + t];
        return;
    }
}

// ---------------------------------------------------------------------------
// K2: fused v + score.
//   Blocks 0..95: (ngrp, ht). Compute v-tile[8n x 32h] (R9 math + cascaded
//   reduction), then partial scores for 8n x 32k over this h-tile ->
//   g_spart[ht][n*32+k]. Block 96: c[n].
//   Last-ticket block (mod 97) finalizes: sum 24 partials + c, mask, write out.
// ---------------------------------------------------------------------------
__global__ void __launch_bounds__(256) k2_vscore(
    const float* __restrict__ W_k,       // (H,H)
    const float* __restrict__ b_k,       // (H,)
    const float* __restrict__ p1,        // (N,K,H)
    const int*   __restrict__ ck_mask,   // (N,K) bool-as-int32
    float* __restrict__ out)
{
    // smem union: sc [0,27648) | red [27648,44032) | vtile [44032,45056)
    __shared__ __align__(16) unsigned char sm[45056];
    __shared__ int s_final;

    float*  sc    = reinterpret_cast<float*>(sm);           // [g][nn] stride 9
    float4* red   = reinterpret_cast<float4*>(sm + 27648);  // 16*64 float4
    float*  vtile = reinterpret_cast<float*>(sm + 44032);   // [nn][32]

    int blk = blockIdx.x;
    int tid = threadIdx.x;

    if (blk < 96) {
        int ngrp = blk / 24;
        int ht   = blk - ngrp * 24;
        int n0   = ngrp * 8;
        int h0   = ht * 32;
        int gsub = tid >> 3;                    // 0..31
        int hf4  = tid & 7;                     // 0..7
        int h    = h0 + hf4 * 4;

        for (int s = tid; s < 8 * HH; s += 256) {
            int nn = s / HH;
            int g  = s - nn * HH;
            sc[g * 9 + nn] = g_cqk[(size_t)(n0 + nn) * HH + g];
        }
        __syncthreads();

        float4 acc[8];
#pragma unroll
        for (int nn = 0; nn < 8; ++nn) acc[nn] = make_float4(0.f, 0.f, 0.f, 0.f);

        int g0 = gsub * 24;
#pragma unroll 6
        for (int i = 0; i < 24; ++i) {
            int g = g0 + i;
            float4 wv = __ldg(reinterpret_cast<const float4*>(W_k + (size_t)g * HH + h));
#pragma unroll
            for (int nn = 0; nn < 8; ++nn) {
                float x = sc[g * 9 + nn];
                acc[nn].x = fmaf(wv.x, x, acc[nn].x);
                acc[nn].y = fmaf(wv.y, x, acc[nn].y);
                acc[nn].z = fmaf(wv.z, x, acc[nn].z);
                acc[nn].w = fmaf(wv.w, x, acc[nn].w);
            }
        }

        // cascaded halving over gsub (32 -> 1)
#pragma unroll
        for (int step = 16; step >= 1; step >>= 1) {
            if (gsub >= step && gsub < 2 * step) {
#pragma unroll
                for (int nn = 0; nn < 8; ++nn)
                    red[(gsub - step) * 64 + hf4 * 8 + nn] = acc[nn];
            }
            __syncthreads();
            if (gsub < step) {
#pragma unroll
                for (int nn = 0; nn < 8; ++nn) {
                    float4 p = red[gsub * 64 + hf4 * 8 + nn];
                    acc[nn].x += p.x; acc[nn].y += p.y;
                    acc[nn].z += p.z; acc[nn].w += p.w;
                }
            }
            __syncthreads();
        }

        if (gsub == 0) {
#pragma unroll
            for (int nn = 0; nn < 8; ++nn)
                *reinterpret_cast<float4*>(&vtile[nn * 32 + hf4 * 4]) = acc[nn];
        }
        __syncthreads();

        // ---- partial scores: thread = (nn = tid>>5, k = tid&31) ----
        {
            int nn = tid >> 5;
            int k  = tid & 31;
            int n  = n0 + nn;
            const float4* prow = reinterpret_cast<const float4*>(
                p1 + ((size_t)n * KK + k) * HH + h0);
            float4 a[8];
#pragma unroll
            for (int i = 0; i < 8; ++i) a[i] = prow[i];
            float s = 0.f;
#pragma unroll
            for (int i = 0; i < 8; ++i) {
                s = fmaf(a[i].x, vtile[nn * 32 + i * 4 + 0], s);
                s = fmaf(a[i].y, vtile[nn * 32 + i * 4 + 1], s);
                s = fmaf(a[i].z, vtile[nn * 32 + i * 4 + 2], s);
                s = fmaf(a[i].w, vtile[nn * 32 + i * 4 + 3], s);
            }
            g_spart[ht * 1024 + n * 32 + k] = s;
        }
    } else {
        // ---- block 96: c[n] = b_k . cqk[n,:] ----
        float* cred = reinterpret_cast<float*>(sm);     // 32*9
        int n = tid >> 3;
        int q = tid & 7;
        float s = 0.f;
        for (int i = 0; i < 96; ++i) {
            int g = q * 96 + i;
            s = fmaf(__ldg(b_k + g), g_cqk[(size_t)n * HH + g], s);
        }
        cred[n * 9 + q] = s;
        __syncthreads();
        if (tid < 32) {
            float t = 0.f;
#pragma unroll
            for (int j = 0; j < 8; ++j) t += cred[tid * 9 + j];
            g_c[tid] = t;
        }
    }

    // ---- last-ticket finalize (no spin; monotonic mod-97) ----
    __threadfence();
    __syncthreads();
    if (tid == 0) {
        unsigned t = atomicAdd(&g_tick, 1u);
        s_final = ((t % 97u) == 96u) ? 1 : 0;
    }
    __syncthreads();
    if (s_final) {
        __threadfence();
#pragma unroll
        for (int u = 0; u < 4; ++u) {
            int idx = tid + u * 256;            // 0..1023
            int n = idx >> 5;
            float s = 0.f;
#pragma unroll 8
            for (int ht = 0; ht < 24; ++ht)
                s += g_spart[ht * 1024 + idx];
            s += g_c[n];
            if (ck_mask[idx] == 0) s = -1e20f;
            out[OFF_SCORE + idx] = s;
        }
    }
}

extern "C" void kernel_launch(void* const* d_in, const int* in_sizes, int n_in,
                              void* d_out, int out_size) {
    const float* ctx     = (const float*)d_in[0];
    const float* tracked = (const float*)d_in[1];
    const float* p0      = (const float*)d_in[2];
    const float* p1      = (const float*)d_in[3];
    const int*   pmask   = (const int*)d_in[4];
    const int*   ckmask  = (const int*)d_in[5];
    const int*   label   = (const int*)d_in[6];
    const int*   ptok    = (const int*)d_in[7];
    const float* W_cqk   = (const float*)d_in[8];
    const float* b_cqk   = (const float*)d_in[9];
    const float* W_k     = (const float*)d_in[10];
    const float* b_k     = (const float*)d_in[11];
    float* out = (float*)d_out;

    k1_fused<<<K1_BLOCKS, 256>>>(ctx, tracked, W_cqk, b_cqk,
                                 p0, p1, pmask, label, ptok, W_k, out);
    k2_vscore<<<97, 256>>>(W_k, b_k, p1, ckmask, out);
}